// round 16
// baseline (speedup 1.0000x reference)
#include <cuda_runtime.h>
#include <cstdint>

// cAttend_simple, histogram + dense-streaming form (no random row gathers):
//   h_b[p] = sum_{i:pos=p} val[b,i]   (K1: 16K spread atomics)
//   u_b    = sum_p h_b[p] embed[p]    (K2: coalesced stream, high MLP)
//   s_b = Wq u_b + bq V_b; w_b = Wk^T s_b; c_b = s_b.bk   (K2 last block)
//   z_b[p] = w_b . embed[p]           (K3: single-wave stream, 4 rows/warp)
//   out    = val*(1+SCALE*(z[pos]+c)) (K3 last block)
// Scratch is self-cleaning: every consumer zeroes what it read, so no zeroing
// kernel is needed and graph replays see the same initial state every time.

#define BB 4
#define NN 4096
#define EE 256
#define DD 64
#define PP 10001           // DATA_DIM + 1 rows
#define SCALE 0.125f
#define K2BLK 128          // u-stream blocks (1024 thr)
#define K3BLK 160          // z-stream blocks (512 thr); 160*16*4 = 10240 >= PP

__device__ float    g_h[PP * BB];    // zero at load; K2 re-zeroes its stripe
__device__ float    g_z[PP * BB];    // fully rewritten every run
__device__ float    g_u[BB * EE];    // zero at load; projection block re-zeroes
__device__ float    g_V[BB];
__device__ float    g_w[BB][EE];
__device__ float    g_c[BB];
__device__ unsigned g_c2 = 0, g_c3 = 0;  // last-block counters, self-resetting

__device__ __forceinline__ float ldcg(const float* p) {
    float r;
    asm volatile("ld.global.cg.f32 %0, [%1];" : "=f"(r) : "l"(p));
    return r;
}

// ---------------------------------------------------------------------------
// K1: histogram scatter (16K spread atomicAdds).
// ---------------------------------------------------------------------------
__global__ void __launch_bounds__(1024) k_hist(const float* __restrict__ val,
                                               const int* __restrict__ pos) {
    const int i = blockIdx.x * 1024 + threadIdx.x;    // i = b*NN + j
    if (i < BB * NN) {
        const int b = i >> 12;
        atomicAdd(&g_h[(size_t)pos[i] * BB + b], val[i]);
    }
}

// ---------------------------------------------------------------------------
// K2: stream embed (float4, 4 rows/block-iter) -> u; self-clean h;
//     last block: projection -> w, c; self-clean u, V, counter.
// grid K2BLK x 1024. thread t: b=t>>8, i=t&255, q=i&63 (float4 col), rr=i>>6.
// ---------------------------------------------------------------------------
__global__ void __launch_bounds__(1024, 1)
k_stream_u(const float* __restrict__ embed, const float* __restrict__ Wq,
           const float* __restrict__ bq, const float* __restrict__ Wk,
           const float* __restrict__ bk) {
    const int t    = threadIdx.x;
    const int blk  = blockIdx.x;
    const int b    = t >> 8;
    const int i    = t & 255;
    const int q    = i & 63;
    const int rr   = i >> 6;
    const int warp = t >> 5;
    const int lane = t & 31;

    const float4* embed4 = (const float4*)embed;

    float4 acc = make_float4(0.f, 0.f, 0.f, 0.f);
    float  vacc = 0.f;
#pragma unroll 2
    for (int p0 = blk * 4; p0 < PP; p0 += K2BLK * 4) {
        const int p = p0 + rr;
        float hv = 0.f;
        float4 e = make_float4(0.f, 0.f, 0.f, 0.f);
        if (p < PP) {
            hv = ldcg(&g_h[(size_t)p * BB + b]);       // warp-uniform broadcast
            e  = __ldg(&embed4[(size_t)p * 64 + q]);   // coalesced 128B/warp
        }
        acc.x += hv * e.x; acc.y += hv * e.y;
        acc.z += hv * e.z; acc.w += hv * e.w;
        vacc += hv;                                    // only q==0's copy is used
    }

    __shared__ float4 sred[1024];
    sred[t] = acc;
    if (q == 0) atomicAdd(&g_V[b], vacc);
    __syncthreads();    // also orders all h reads before the cleaning below

    if (rr == 0) {
        const float4 a0 = sred[t],       a1 = sred[t + 64];
        const float4 a2 = sred[t + 128], a3 = sred[t + 192];
        const int base = b * EE + q * 4;
        atomicAdd(&g_u[base + 0], (a0.x + a1.x) + (a2.x + a3.x));
        atomicAdd(&g_u[base + 1], (a0.y + a1.y) + (a2.y + a3.y));
        atomicAdd(&g_u[base + 2], (a0.z + a1.z) + (a2.z + a3.z));
        atomicAdd(&g_u[base + 3], (a0.w + a1.w) + (a2.w + a3.w));
    }

    // Self-clean this block's h stripe (sole reader of these entries).
    if (t < 16) {
        for (int p0 = blk * 4; p0 < PP; p0 += K2BLK * 4) {
            const int p = p0 + (t >> 2);
            if (p < PP) g_h[(size_t)p * BB + (t & 3)] = 0.f;
        }
    }

    __threadfence();
    __syncthreads();
    __shared__ unsigned is_last;
    if (t == 0) is_last = (atomicAdd(&g_c2, 1) == K2BLK - 1) ? 1u : 0u;
    __syncthreads();
    if (!is_last) return;
    __threadfence();

    // ---- projection (one block) ----
    __shared__ float su[BB][EE];
    __shared__ float ss[BB][DD];
    __shared__ float sV[BB];
    su[b][i] = ldcg(&g_u[t]);
    if (t < BB) sV[t] = ldcg(&g_V[t]);
    __syncthreads();

    // self-clean u, V, counter for the next run (values captured in smem)
    g_u[t] = 0.f;
    if (t < BB) g_V[t] = 0.f;
    if (t == 0) g_c2 = 0;

    // s[b][d] = Wq[d,:].u_b + bq[d]*V_b  (batch b's 8 warps cover d)
    {
        const int wg = warp & 7;
#pragma unroll
        for (int d = wg; d < DD; d += 8) {
            float a = 0.f;
#pragma unroll
            for (int e = lane; e < EE; e += 32) a += __ldg(&Wq[d * EE + e]) * su[b][e];
#pragma unroll
            for (int o = 16; o; o >>= 1) a += __shfl_xor_sync(0xffffffffu, a, o);
            if (lane == 0) ss[b][d] = a + __ldg(&bq[d]) * sV[b];
        }
    }
    __syncthreads();

    // w[b][col] = sum_d Wk[d][col]*s[b][d]
    {
        float w = 0.f;
#pragma unroll 8
        for (int d = 0; d < DD; d++) w += __ldg(&Wk[d * EE + i]) * ss[b][d];
        g_w[b][i] = w;
    }
    // c[b] = s_b . bk
    if (warp < BB) {
        float c = ss[warp][lane] * __ldg(&bk[lane])
                + ss[warp][lane + 32] * __ldg(&bk[lane + 32]);
#pragma unroll
        for (int o = 16; o; o >>= 1) c += __shfl_xor_sync(0xffffffffu, c, o);
        if (lane == 0) g_c[warp] = c;
    }
}

// ---------------------------------------------------------------------------
// K3: single-wave stream embed -> z[p][b], exactly 4 rows per warp
// (8 LDG.128 in flight per lane, no loop-carried dependency);
// last block: output lookups.  grid K3BLK x 512.
// ---------------------------------------------------------------------------
__global__ void __launch_bounds__(512, 1)
k_z_out(const float* __restrict__ val, const int* __restrict__ pos,
        const float* __restrict__ embed, float* __restrict__ out) {
    const int t    = threadIdx.x;
    const int blk  = blockIdx.x;
    const int warp = t >> 5;   // 0..15
    const int lane = t & 31;

    __shared__ float sw[BB][EE];
    __shared__ float sc[BB];
    for (int idx = t; idx < BB * EE; idx += 512)
        sw[idx >> 8][idx & 255] = ldcg(&g_w[idx >> 8][idx & 255]);
    if (t < BB) sc[t] = ldcg(&g_c[t]);
    __syncthreads();

    const float4 w00 = ((const float4*)sw[0])[lane], w01 = ((const float4*)sw[0])[lane + 32];
    const float4 w10 = ((const float4*)sw[1])[lane], w11 = ((const float4*)sw[1])[lane + 32];
    const float4 w20 = ((const float4*)sw[2])[lane], w21 = ((const float4*)sw[2])[lane + 32];
    const float4 w30 = ((const float4*)sw[3])[lane], w31 = ((const float4*)sw[3])[lane + 32];

    {
        const int r0 = (blk * 16 + warp) * 4;       // single pass covers PP
        float4 a0[4], a1[4];
#pragma unroll
        for (int i = 0; i < 4; i++) {               // 8 LDG.128 in flight / lane
            const int p = r0 + i;
            if (p < PP) {
                const float4* er = (const float4*)(embed + (size_t)p * EE);
                a0[i] = __ldg(&er[lane]);
                a1[i] = __ldg(&er[lane + 32]);
            }
        }
#pragma unroll
        for (int i = 0; i < 4; i++) {
            const int p = r0 + i;
            if (p < PP) {
                float d0 = a0[i].x*w00.x + a0[i].y*w00.y + a0[i].z*w00.z + a0[i].w*w00.w
                         + a1[i].x*w01.x + a1[i].y*w01.y + a1[i].z*w01.z + a1[i].w*w01.w;
                float d1 = a0[i].x*w10.x + a0[i].y*w10.y + a0[i].z*w10.z + a0[i].w*w10.w
                         + a1[i].x*w11.x + a1[i].y*w11.y + a1[i].z*w11.z + a1[i].w*w11.w;
                float d2 = a0[i].x*w20.x + a0[i].y*w20.y + a0[i].z*w20.z + a0[i].w*w20.w
                         + a1[i].x*w21.x + a1[i].y*w21.y + a1[i].z*w21.z + a1[i].w*w21.w;
                float d3 = a0[i].x*w30.x + a0[i].y*w30.y + a0[i].z*w30.z + a0[i].w*w30.w
                         + a1[i].x*w31.x + a1[i].y*w31.y + a1[i].z*w31.z + a1[i].w*w31.w;
#pragma unroll
                for (int o = 16; o; o >>= 1) {
                    d0 += __shfl_xor_sync(0xffffffffu, d0, o);
                    d1 += __shfl_xor_sync(0xffffffffu, d1, o);
                    d2 += __shfl_xor_sync(0xffffffffu, d2, o);
                    d3 += __shfl_xor_sync(0xffffffffu, d3, o);
                }
                if (lane == 0) ((float4*)g_z)[p] = make_float4(d0, d1, d2, d3);
            }
        }
    }

    __threadfence();
    __syncthreads();
    __shared__ unsigned is_last;
    if (t == 0) is_last = (atomicAdd(&g_c3, 1) == K3BLK - 1) ? 1u : 0u;
    __syncthreads();
    if (!is_last) return;
    __threadfence();
    if (t == 0) g_c3 = 0;    // self-reset for next run

    // ---- output: 16K O(1) lookups (z is L2-hot, 160KB) ----
#pragma unroll 8
    for (int idx = t; idx < BB * NN; idx += 512) {
        const int b = idx >> 12;
        const int p = __ldg(&pos[idx]);
        const float z = ldcg(&g_z[(size_t)p * BB + b]);
        const float v = __ldg(&val[idx]);
        out[idx] = v + v * (SCALE * (z + sc[b]));
    }
}

// ---------------------------------------------------------------------------
extern "C" void kernel_launch(void* const* d_in, const int* in_sizes, int n_in,
                              void* d_out, int out_size) {
    // metadata order: t, val, pos, embed, Wq, bq, Wk, bk
    const int base = n_in - 7;
    const float* val   = (const float*)d_in[base + 0];
    const int*   pos   = (const int*)  d_in[base + 1];
    const float* embed = (const float*)d_in[base + 2];
    const float* Wq    = (const float*)d_in[base + 3];
    const float* bq    = (const float*)d_in[base + 4];
    const float* Wk    = (const float*)d_in[base + 5];
    const float* bk    = (const float*)d_in[base + 6];
    float* out = (float*)d_out;

    k_hist<<<(BB * NN + 1023) / 1024, 1024>>>(val, pos);
    k_stream_u<<<K2BLK, 1024>>>(embed, Wq, bq, Wk, bk);
    k_z_out<<<K3BLK, 512>>>(val, pos, embed, out);
}